// round 15
// baseline (speedup 1.0000x reference)
#include <cuda_runtime.h>
#include <cuda_fp16.h>

#define MAX_NODES (1 << 17)
// Zero-initialized at module load. INVARIANT: zero at entry of every
// kernel_launch call; mlp_kernel re-zeroes each element after consuming it.
__device__ float  g_lf[MAX_NODES];
__device__ __half g_xh[MAX_NODES];   // fp16 x staging (slice-converted by edge CTAs)
__device__ int    g_bar;             // grid barrier arrival counter (self-resetting)
__device__ int    g_phase;           // grid barrier sense (flips each use)

// Fused prep+edge persistent kernel. 148 CTAs x 512 threads, 1 CTA/SM, all
// resident -> grid barrier is deadlock-free.
// Phase A: slice-convert x -> g_xh; per-CTA index-width detect.
// Barrier. Phase B: broadcast-fill smem fp16 table; stream edges doing
// S[row] += (float)x_h[col] (4 edges/thread, no spills).
__global__ void __launch_bounds__(512, 1)
edge_kernel(const float* __restrict__ x,
            const void* __restrict__ ei, long long E, int n) {
    extern __shared__ __half sx[];
    __shared__ int s_flag[4];

    // --- phase A: convert this CTA's slice of x into g_xh ---
    {
        int chunk = (n + gridDim.x - 1) / gridDim.x;
        int lo = blockIdx.x * chunk;
        int hi = min(n, lo + chunk);
        for (int i = lo + (int)threadIdx.x; i < hi; i += blockDim.x)
            g_xh[i] = __float2half(x[i]);
    }

    // --- local index-width detect: warps 0-3 scan first 128 int64 views ---
    if (threadIdx.x < 128) {
        const long long* p = (const long long*)ei;
        long long v = p[threadIdx.x];
        int is_bad = (v < 0 || v >= (long long)n) ? 1 : 0;
        unsigned m = __ballot_sync(0xFFFFFFFFu, is_bad);
        if ((threadIdx.x & 31) == 0) s_flag[threadIdx.x >> 5] = (m != 0);
    }

    // --- grid barrier (sense-reversal; self-resetting across graph replays) ---
    __threadfence();
    __syncthreads();
    if (threadIdx.x == 0) {
        int ph = *(volatile int*)&g_phase;
        if (atomicAdd(&g_bar, 1) == (int)gridDim.x - 1) {
            g_bar = 0;
            __threadfence();
            *(volatile int*)&g_phase = ph ^ 1;
        } else {
            while (*(volatile int*)&g_phase == ph) { }
        }
    }
    __syncthreads();
    __threadfence();

    // --- phase B: broadcast-fill smem table from g_xh (fp16, L2-resident) ---
    {
        int nchunk = (n * 2 + 15) >> 4;   // 16B chunks (g_xh zero-padded past n)
        const int4* src = reinterpret_cast<const int4*>(g_xh);
        int4* dst = reinterpret_cast<int4*>(sx);
        for (int i = threadIdx.x; i < nchunk; i += blockDim.x) dst[i] = src[i];
    }
    __syncthreads();

    int is32 = s_flag[0] | s_flag[1] | s_flag[2] | s_flag[3];

    long long nvec = E >> 2;
    long long stride = (long long)gridDim.x * blockDim.x;

    for (long long t = (long long)blockIdx.x * blockDim.x + threadIdx.x;
         t < nvec; t += stride) {
        long long base = t << 2;
        int r[4], c[4];
        if (is32) {
            const int* rows = (const int*)ei;
            const int* cols = rows + E;
            int4 ra = *reinterpret_cast<const int4*>(rows + base);
            int4 ca = *reinterpret_cast<const int4*>(cols + base);
            r[0] = ra.x; r[1] = ra.y; r[2] = ra.z; r[3] = ra.w;
            c[0] = ca.x; c[1] = ca.y; c[2] = ca.z; c[3] = ca.w;
        } else {
            const long long* rows = (const long long*)ei;
            const long long* cols = rows + E;
            longlong2 ra = *reinterpret_cast<const longlong2*>(rows + base);
            longlong2 rb = *reinterpret_cast<const longlong2*>(rows + base + 2);
            longlong2 ca = *reinterpret_cast<const longlong2*>(cols + base);
            longlong2 cb = *reinterpret_cast<const longlong2*>(cols + base + 2);
            r[0] = (int)ra.x; r[1] = (int)ra.y; r[2] = (int)rb.x; r[3] = (int)rb.y;
            c[0] = (int)ca.x; c[1] = (int)ca.y; c[2] = (int)cb.x; c[3] = (int)cb.y;
        }
        float v[4];
#pragma unroll
        for (int k = 0; k < 4; k++) v[k] = __half2float(sx[c[k]]);
#pragma unroll
        for (int k = 0; k < 4; k++) atomicAdd(&g_lf[r[k]], v[k]);
    }

    // tail (E not divisible by 4)
    if (blockIdx.x == 0 && threadIdx.x == 0) {
        for (long long e = nvec << 2; e < E; e++) {
            int rr, cc;
            if (is32) {
                const int* rows = (const int*)ei;
                rr = rows[e]; cc = rows[E + e];
            } else {
                const long long* rows = (const long long*)ei;
                rr = (int)rows[e]; cc = (int)rows[E + e];
            }
            atomicAdd(&g_lf[rr], __half2float(sx[cc]));
        }
    }
}

// Two nodes per thread (i, i+blockDim): w2 read as float4 from smem.
// lf = x[i] * S[i] (factored multiply). Re-zeroes g_lf after consuming it
// to maintain the zero-invariant for the next graph replay.
__global__ void mlp_kernel(const float* __restrict__ x,
                           const float* __restrict__ w1,
                           const float* __restrict__ b1,
                           const float* __restrict__ w2,
                           const float* __restrict__ b2,
                           float* __restrict__ out,
                           int n) {
    __shared__ float sw1[32];
    __shared__ float sb1[16];
    __shared__ __align__(16) float sw2[256];
    __shared__ float sb2[16];

    int tid = threadIdx.x;
    if (tid < 32) sw1[tid] = w1[tid];
    if (tid < 16) sb1[tid] = b1[tid];
    if (tid >= 16 && tid < 32) sb2[tid - 16] = b2[tid - 16];
    for (int i = tid; i < 256; i += blockDim.x) sw2[i] = w2[i];
    __syncthreads();

    int ia = blockIdx.x * (blockDim.x * 2) + tid;
    int ib = ia + blockDim.x;
    bool vb = (ib < n);
    if (ia >= n) return;

    float xa = x[ia];
    float lfa = xa * g_lf[ia];
    g_lf[ia] = 0.0f;
    float xb = 0.f, lfb = 0.f;
    if (vb) {
        xb = x[ib];
        lfb = xb * g_lf[ib];
        g_lf[ib] = 0.0f;
    }

    float ha[16], hb[16];
#pragma unroll
    for (int j = 0; j < 16; j++) {
        float w0 = sw1[2 * j], w1v = sw1[2 * j + 1], bj = sb1[j];
        ha[j] = fmaxf(fmaf(xa, w0, fmaf(lfa, w1v, bj)), 0.0f);
        hb[j] = fmaxf(fmaf(xb, w0, fmaf(lfb, w1v, bj)), 0.0f);
    }

    const float4* sw24 = reinterpret_cast<const float4*>(sw2);
    float oa[16], ob[16];
#pragma unroll
    for (int k = 0; k < 16; k++) {
        float sa = sb2[k], sb = sa;
#pragma unroll
        for (int jj = 0; jj < 4; jj++) {
            float4 w = sw24[k * 4 + jj];
            int j = jj * 4;
            sa = fmaf(ha[j],     w.x, sa);  sb = fmaf(hb[j],     w.x, sb);
            sa = fmaf(ha[j + 1], w.y, sa);  sb = fmaf(hb[j + 1], w.y, sb);
            sa = fmaf(ha[j + 2], w.z, sa);  sb = fmaf(hb[j + 2], w.z, sb);
            sa = fmaf(ha[j + 3], w.w, sa);  sb = fmaf(hb[j + 3], w.w, sb);
        }
        oa[k] = fmaxf(sa, 0.0f);
        ob[k] = fmaxf(sb, 0.0f);
    }

    float4* o4a = reinterpret_cast<float4*>(out + (size_t)ia * 16);
    o4a[0] = make_float4(oa[0],  oa[1],  oa[2],  oa[3]);
    o4a[1] = make_float4(oa[4],  oa[5],  oa[6],  oa[7]);
    o4a[2] = make_float4(oa[8],  oa[9],  oa[10], oa[11]);
    o4a[3] = make_float4(oa[12], oa[13], oa[14], oa[15]);
    if (vb) {
        float4* o4b = reinterpret_cast<float4*>(out + (size_t)ib * 16);
        o4b[0] = make_float4(ob[0],  ob[1],  ob[2],  ob[3]);
        o4b[1] = make_float4(ob[4],  ob[5],  ob[6],  ob[7]);
        o4b[2] = make_float4(ob[8],  ob[9],  ob[10], ob[11]);
        o4b[3] = make_float4(ob[12], ob[13], ob[14], ob[15]);
    }
}

extern "C" void kernel_launch(void* const* d_in, const int* in_sizes, int n_in,
                              void* d_out, int out_size) {
    const float* x  = (const float*)d_in[0];
    const void*  ei = d_in[1];
    const float* w1 = (const float*)d_in[2];
    const float* b1 = (const float*)d_in[3];
    const float* w2 = (const float*)d_in[4];
    const float* b2 = (const float*)d_in[5];
    float*       out = (float*)d_out;

    int n = in_sizes[0];                        // x is [N, 1]
    long long E = (long long)in_sizes[1] / 2;   // edge_index is [2, E]

    size_t smem_bytes = ((size_t)n * 2 + 15) & ~(size_t)15;
    cudaFuncSetAttribute(edge_kernel,
                         cudaFuncAttributeMaxDynamicSharedMemorySize,
                         (int)smem_bytes);

    edge_kernel<<<148, 512, smem_bytes>>>(x, ei, E, n);

    int mlp_tpb = 256;   // 512 nodes per block
    int mlp_blocks = (n + mlp_tpb * 2 - 1) / (mlp_tpb * 2);
    mlp_kernel<<<mlp_blocks, mlp_tpb>>>(x, w1, b1, w2, b2, out, n);
}

// round 16
// speedup vs baseline: 1.9093x; 1.9093x over previous
#include <cuda_runtime.h>
#include <cuda_fp16.h>

#define MAX_NODES (1 << 17)
// Zero-initialized at module load. INVARIANT: zero at entry of every
// kernel_launch call; mlp_kernel re-zeroes each element after consuming it.
__device__ float  g_lf[MAX_NODES];
__device__ __half g_xh[MAX_NODES];   // fp16 x for smem gather table
__device__ int    g_is32;            // 1 if edge_index is int32, 0 if int64

// Prep: build fp16 table + detect index width. (No zeroing — invariant.)
__global__ void prep_kernel(const float* __restrict__ x,
                            const void* __restrict__ ei, int n) {
    int i4 = blockIdx.x * blockDim.x + threadIdx.x;   // one float4 (4 nodes)
    int base = i4 * 4;
    if (base < n) {
        if (base + 3 < n) {
            float4 xv = *reinterpret_cast<const float4*>(x + base);
            *reinterpret_cast<__half2*>(g_xh + base)     = __floats2half2_rn(xv.x, xv.y);
            *reinterpret_cast<__half2*>(g_xh + base + 2) = __floats2half2_rn(xv.z, xv.w);
        } else {
            for (int k = base; k < n; k++) g_xh[k] = __float2half(x[k]);
        }
    }
    if (blockIdx.x == 0) {
        __shared__ int bad;
        if (threadIdx.x == 0) bad = 0;
        __syncthreads();
        if (threadIdx.x < 128) {
            const long long* p = (const long long*)ei;
            long long v = p[threadIdx.x];
            int is_bad = (v < 0 || v >= (long long)n) ? 1 : 0;
            unsigned m = __ballot_sync(0xFFFFFFFFu, is_bad);
            if ((threadIdx.x & 31) == 0 && m) atomicOr(&bad, 1);
        }
        __syncthreads();
        if (threadIdx.x == 0) g_is32 = bad;   // out-of-range int64 => really int32
    }
}

// Persistent edge kernel (PROVEN FORM — do not add body code):
// stage fp16 x table in smem, stream edges, S[row] += (float)x_h[col].
// 512 threads, 4 edges/thread.
__global__ void __launch_bounds__(512, 1)
edge_kernel(const void* __restrict__ ei, long long E, int n) {
    extern __shared__ __half sx[];

    int nchunk = (n * 2 + 15) >> 4;
    const int4* src = reinterpret_cast<const int4*>(g_xh);
    int4* dst = reinterpret_cast<int4*>(sx);
    for (int i = threadIdx.x; i < nchunk; i += blockDim.x) dst[i] = src[i];
    __syncthreads();

    int is32 = g_is32;
    long long nvec = E >> 2;
    long long stride = (long long)gridDim.x * blockDim.x;

    for (long long t = (long long)blockIdx.x * blockDim.x + threadIdx.x;
         t < nvec; t += stride) {
        long long base = t << 2;
        int r[4], c[4];
        if (is32) {
            const int* rows = (const int*)ei;
            const int* cols = rows + E;
            int4 ra = *reinterpret_cast<const int4*>(rows + base);
            int4 ca = *reinterpret_cast<const int4*>(cols + base);
            r[0] = ra.x; r[1] = ra.y; r[2] = ra.z; r[3] = ra.w;
            c[0] = ca.x; c[1] = ca.y; c[2] = ca.z; c[3] = ca.w;
        } else {
            const long long* rows = (const long long*)ei;
            const long long* cols = rows + E;
            longlong2 ra = *reinterpret_cast<const longlong2*>(rows + base);
            longlong2 rb = *reinterpret_cast<const longlong2*>(rows + base + 2);
            longlong2 ca = *reinterpret_cast<const longlong2*>(cols + base);
            longlong2 cb = *reinterpret_cast<const longlong2*>(cols + base + 2);
            r[0] = (int)ra.x; r[1] = (int)ra.y; r[2] = (int)rb.x; r[3] = (int)rb.y;
            c[0] = (int)ca.x; c[1] = (int)ca.y; c[2] = (int)cb.x; c[3] = (int)cb.y;
        }
        float v[4];
#pragma unroll
        for (int k = 0; k < 4; k++) v[k] = __half2float(sx[c[k]]);
#pragma unroll
        for (int k = 0; k < 4; k++) atomicAdd(&g_lf[r[k]], v[k]);
    }

    if (blockIdx.x == 0 && threadIdx.x == 0) {
        for (long long e = nvec << 2; e < E; e++) {
            int rr, cc;
            if (is32) {
                const int* rows = (const int*)ei;
                rr = rows[e]; cc = rows[E + e];
            } else {
                const long long* rows = (const long long*)ei;
                rr = (int)rows[e]; cc = (int)rows[E + e];
            }
            atomicAdd(&g_lf[rr], __half2float(sx[cc]));
        }
    }
}

// Persistent-ish MLP: 296 CTAs (2/SM), grid-stride over nodes. Weights
// staged once per CTA (2 ramps/SM instead of ~2.6 waves of ramps).
// lf = x[i] * S[i] (factored multiply). Re-zeroes g_lf after consuming it
// to maintain the zero-invariant for the next graph replay.
__global__ void __launch_bounds__(256)
mlp_kernel(const float* __restrict__ x,
           const float* __restrict__ w1,
           const float* __restrict__ b1,
           const float* __restrict__ w2,
           const float* __restrict__ b2,
           float* __restrict__ out,
           int n) {
    __shared__ float sw1[32];
    __shared__ float sb1[16];
    __shared__ __align__(16) float sw2[256];
    __shared__ float sb2[16];

    int tid = threadIdx.x;
    if (tid < 32) sw1[tid] = w1[tid];
    if (tid < 16) sb1[tid] = b1[tid];
    if (tid >= 16 && tid < 32) sb2[tid - 16] = b2[tid - 16];
    for (int i = tid; i < 256; i += blockDim.x) sw2[i] = w2[i];
    __syncthreads();

    const float4* sw24 = reinterpret_cast<const float4*>(sw2);
    int gstride = gridDim.x * blockDim.x;

    for (int i = blockIdx.x * blockDim.x + tid; i < n; i += gstride) {
        float xv = x[i];
        float lf = xv * g_lf[i];
        g_lf[i] = 0.0f;

        float h[16];
#pragma unroll
        for (int j = 0; j < 16; j++) {
            float v = fmaf(xv, sw1[2 * j], fmaf(lf, sw1[2 * j + 1], sb1[j]));
            h[j] = fmaxf(v, 0.0f);
        }

        float o[16];
#pragma unroll
        for (int k = 0; k < 16; k++) {
            float s = sb2[k];
#pragma unroll
            for (int jj = 0; jj < 4; jj++) {
                float4 w = sw24[k * 4 + jj];
                int j = jj * 4;
                s = fmaf(h[j],     w.x, s);
                s = fmaf(h[j + 1], w.y, s);
                s = fmaf(h[j + 2], w.z, s);
                s = fmaf(h[j + 3], w.w, s);
            }
            o[k] = fmaxf(s, 0.0f);
        }

        float4* o4 = reinterpret_cast<float4*>(out + (size_t)i * 16);
        o4[0] = make_float4(o[0],  o[1],  o[2],  o[3]);
        o4[1] = make_float4(o[4],  o[5],  o[6],  o[7]);
        o4[2] = make_float4(o[8],  o[9],  o[10], o[11]);
        o4[3] = make_float4(o[12], o[13], o[14], o[15]);
    }
}

extern "C" void kernel_launch(void* const* d_in, const int* in_sizes, int n_in,
                              void* d_out, int out_size) {
    const float* x  = (const float*)d_in[0];
    const void*  ei = d_in[1];
    const float* w1 = (const float*)d_in[2];
    const float* b1 = (const float*)d_in[3];
    const float* w2 = (const float*)d_in[4];
    const float* b2 = (const float*)d_in[5];
    float*       out = (float*)d_out;

    int n = in_sizes[0];                        // x is [N, 1]
    long long E = (long long)in_sizes[1] / 2;   // edge_index is [2, E]

    size_t smem_bytes = ((size_t)n * 2 + 15) & ~(size_t)15;
    cudaFuncSetAttribute(edge_kernel,
                         cudaFuncAttributeMaxDynamicSharedMemorySize,
                         (int)smem_bytes);

    int prep_threads = (n + 3) / 4;
    prep_kernel<<<(prep_threads + 255) / 256, 256>>>(x, ei, n);
    edge_kernel<<<148, 512, smem_bytes>>>(ei, E, n);
    mlp_kernel<<<296, 256>>>(x, w1, b1, w2, b2, out, n);
}